// round 1
// baseline (speedup 1.0000x reference)
#include <cuda_runtime.h>
#include <cstdint>

#define N_NODES 50000
#define DIM 128
#define ODIM 64

// Scratch (static device globals; no allocation).
__device__ float g_h[(size_t)N_NODES * DIM];     // layer activations
__device__ float g_agg[(size_t)N_NODES * DIM];   // aggregation / pre-scatter buffer
__device__ float g_norm_src[N_NODES];
__device__ float g_norm_dst[N_NODES];
__device__ float g_outdeg[N_NODES];
__device__ float g_indeg[N_NODES];

// ---------------------------------------------------------------------------
// Degree / norm kernels
// ---------------------------------------------------------------------------
__global__ void zero_deg_kernel() {
    int i = blockIdx.x * blockDim.x + threadIdx.x;
    if (i < N_NODES) { g_outdeg[i] = 0.f; g_indeg[i] = 0.f; }
}

__global__ void deg_kernel(const int* __restrict__ src, const int* __restrict__ dst, int E) {
    int i = blockIdx.x * blockDim.x + threadIdx.x;
    if (i < E) {
        atomicAdd(&g_outdeg[src[i]], 1.f);
        atomicAdd(&g_indeg[dst[i]], 1.f);
    }
}

__global__ void norm_kernel() {
    int i = blockIdx.x * blockDim.x + threadIdx.x;
    if (i < N_NODES) {
        g_norm_src[i] = rsqrtf(fmaxf(g_outdeg[i], 1.f));
        g_norm_dst[i] = rsqrtf(fmaxf(g_indeg[i], 1.f));
    }
}

__global__ void zero_kernel(float* __restrict__ p, int n4) {
    int i = blockIdx.x * blockDim.x + threadIdx.x;
    if (i < n4) reinterpret_cast<float4*>(p)[i] = make_float4(0.f, 0.f, 0.f, 0.f);
}

// ---------------------------------------------------------------------------
// Edge scatter: one warp per edge (128 dims), vectorized L2 reduction
// ---------------------------------------------------------------------------
template <bool SCALE_SRC>
__global__ void scatter128_kernel(const float* __restrict__ x,
                                  const int* __restrict__ src,
                                  const int* __restrict__ dst,
                                  float* __restrict__ agg, int E) {
    int w = (blockIdx.x * blockDim.x + threadIdx.x) >> 5;
    if (w >= E) return;
    int lane = threadIdx.x & 31;
    int s = __ldg(src + w);
    int d = __ldg(dst + w);
    float4 v = __ldg(reinterpret_cast<const float4*>(x + (size_t)s * DIM) + lane);
    if (SCALE_SRC) {
        float sc = __ldg(&g_norm_src[s]);
        v.x *= sc; v.y *= sc; v.z *= sc; v.w *= sc;
    }
    float* p = agg + (size_t)d * DIM + lane * 4;
    asm volatile("red.global.add.v4.f32 [%0], {%1, %2, %3, %4};"
                 :: "l"(p), "f"(v.x), "f"(v.y), "f"(v.z), "f"(v.w) : "memory");
}

// 64-dim scatter: half-warp per edge
__global__ void scatter64_kernel(const float* __restrict__ x,
                                 const int* __restrict__ src,
                                 const int* __restrict__ dst,
                                 float* __restrict__ agg, int E) {
    int t = blockIdx.x * blockDim.x + threadIdx.x;
    int e = t >> 4;
    if (e >= E) return;
    int sub = t & 15;
    int s = __ldg(src + e);
    int d = __ldg(dst + e);
    float4 v = __ldg(reinterpret_cast<const float4*>(x + (size_t)s * ODIM) + sub);
    float* p = agg + (size_t)d * ODIM + sub * 4;
    asm volatile("red.global.add.v4.f32 [%0], {%1, %2, %3, %4};"
                 :: "l"(p), "f"(v.x), "f"(v.y), "f"(v.z), "f"(v.w) : "memory");
}

// ---------------------------------------------------------------------------
// Register-tiled FP32 GEMM: out = post_scale * act(pre_scale*in @ W + bias)
// Block: 64 rows x COUT cols. Thread: 8 rows x 4 cols.
// ---------------------------------------------------------------------------
template <int CIN, int COUT, bool RELU, bool BIAS>
__global__ void gemm_kernel(const float* __restrict__ in,
                            const float* __restrict__ W,
                            const float* __restrict__ bias,
                            const float* __restrict__ pre_scale,
                            const float* __restrict__ post_scale,
                            float* __restrict__ out, int nrows) {
    constexpr int ROWS = 64;
    constexpr int KC   = 32;
    constexpr int CT   = COUT / 4;   // col-thread groups
    constexpr int RG   = 8;          // row groups
    constexpr int RPT  = ROWS / RG;  // rows per thread = 8
    constexpr int NT   = CT * RG;    // threads per block

    __shared__ float sW[KC][COUT];
    __shared__ float sX[ROWS][KC];

    const int tid  = threadIdx.x;
    const int c    = tid % CT;
    const int rg   = tid / CT;
    const int row0 = blockIdx.x * ROWS;

    float acc[RPT][4];
#pragma unroll
    for (int r = 0; r < RPT; r++) {
        acc[r][0] = 0.f; acc[r][1] = 0.f; acc[r][2] = 0.f; acc[r][3] = 0.f;
    }

    for (int k0 = 0; k0 < CIN; k0 += KC) {
        // stage W chunk (contiguous KC*COUT floats)
#pragma unroll
        for (int i = tid; i < KC * COUT / 4; i += NT)
            reinterpret_cast<float4*>(&sW[0][0])[i] =
                __ldg(reinterpret_cast<const float4*>(W + (size_t)k0 * COUT) + i);
        // stage X tile (with optional per-row pre-scale)
#pragma unroll
        for (int i = tid; i < ROWS * KC / 4; i += NT) {
            int r  = i / (KC / 4);
            int kk = i % (KC / 4);
            int row = row0 + r;
            float4 v = make_float4(0.f, 0.f, 0.f, 0.f);
            if (row < nrows) {
                v = __ldg(reinterpret_cast<const float4*>(in + (size_t)row * CIN + k0) + kk);
                if (pre_scale) {
                    float ps = __ldg(&pre_scale[row]);
                    v.x *= ps; v.y *= ps; v.z *= ps; v.w *= ps;
                }
            }
            reinterpret_cast<float4*>(&sX[r][0])[kk] = v;
        }
        __syncthreads();
#pragma unroll
        for (int k = 0; k < KC; k++) {
            float4 w = *reinterpret_cast<const float4*>(&sW[k][c * 4]);
#pragma unroll
            for (int r = 0; r < RPT; r++) {
                float xv = sX[rg * RPT + r][k];
                acc[r][0] = fmaf(xv, w.x, acc[r][0]);
                acc[r][1] = fmaf(xv, w.y, acc[r][1]);
                acc[r][2] = fmaf(xv, w.z, acc[r][2]);
                acc[r][3] = fmaf(xv, w.w, acc[r][3]);
            }
        }
        __syncthreads();
    }

    float4 bv = make_float4(0.f, 0.f, 0.f, 0.f);
    if (BIAS) bv = __ldg(reinterpret_cast<const float4*>(bias) + c);

#pragma unroll
    for (int r = 0; r < RPT; r++) {
        int row = row0 + rg * RPT + r;
        if (row >= nrows) continue;
        float4 o;
        o.x = acc[r][0] + bv.x;
        o.y = acc[r][1] + bv.y;
        o.z = acc[r][2] + bv.z;
        o.w = acc[r][3] + bv.w;
        if (RELU) {
            o.x = fmaxf(o.x, 0.f); o.y = fmaxf(o.y, 0.f);
            o.z = fmaxf(o.z, 0.f); o.w = fmaxf(o.w, 0.f);
        }
        if (post_scale) {
            float ps = __ldg(&post_scale[row]);
            o.x *= ps; o.y *= ps; o.z *= ps; o.w *= ps;
        }
        *reinterpret_cast<float4*>(out + (size_t)row * COUT + c * 4) = o;
    }
}

// final: out = out * norm_dst[row] + b3
__global__ void finalize_kernel(float* __restrict__ out, const float* __restrict__ b3) {
    int t = blockIdx.x * blockDim.x + threadIdx.x;
    constexpr int J = ODIM / 4;
    if (t >= N_NODES * J) return;
    int i = t / J;
    int j = t % J;
    float nd = g_norm_dst[i];
    float4* p = reinterpret_cast<float4*>(out + (size_t)i * ODIM) + j;
    float4 v = *p;
    float4 b = __ldg(reinterpret_cast<const float4*>(b3) + j);
    v.x = fmaf(v.x, nd, b.x);
    v.y = fmaf(v.y, nd, b.y);
    v.z = fmaf(v.z, nd, b.z);
    v.w = fmaf(v.w, nd, b.w);
    *p = v;
}

// ---------------------------------------------------------------------------
extern "C" void kernel_launch(void* const* d_in, const int* in_sizes, int n_in,
                              void* d_out, int out_size) {
    const float* features = (const float*)d_in[0];
    const float* W1 = (const float*)d_in[1];
    const float* b1 = (const float*)d_in[2];
    const float* W2 = (const float*)d_in[3];
    const float* b2 = (const float*)d_in[4];
    const float* W3 = (const float*)d_in[5];
    const float* b3 = (const float*)d_in[6];
    const int* src  = (const int*)d_in[7];
    const int* dst  = (const int*)d_in[8];
    const int E = in_sizes[7];
    float* out = (float*)d_out;

    float *h, *agg, *nsrc, *ndst;
    cudaGetSymbolAddress((void**)&h,    g_h);
    cudaGetSymbolAddress((void**)&agg,  g_agg);
    cudaGetSymbolAddress((void**)&nsrc, g_norm_src);
    cudaGetSymbolAddress((void**)&ndst, g_norm_dst);

    const int TB = 256;
    // degrees + norms
    zero_deg_kernel<<<(N_NODES + TB - 1) / TB, TB>>>();
    deg_kernel<<<(E + TB - 1) / TB, TB>>>(src, dst, E);
    norm_kernel<<<(N_NODES + TB - 1) / TB, TB>>>();

    const int n4 = N_NODES * DIM / 4;
    const int gemm_blocks = (N_NODES + 63) / 64;

    // Layer 1: agg = segsum(norm_src*features); h = norm_src * relu(agg*norm_dst @ W1 + b1)
    zero_kernel<<<(n4 + TB - 1) / TB, TB>>>(agg, n4);
    scatter128_kernel<true><<<(E * 32 + TB - 1) / TB, TB>>>(features, src, dst, agg, E);
    gemm_kernel<128, 128, true, true><<<gemm_blocks, 256>>>(agg, W1, b1, ndst, nsrc, h, N_NODES);

    // Layer 2: agg = segsum(h); h2 = relu(agg*norm_dst @ W2 + b2)   (norm_src already folded)
    zero_kernel<<<(n4 + TB - 1) / TB, TB>>>(agg, n4);
    scatter128_kernel<false><<<(E * 32 + TB - 1) / TB, TB>>>(h, src, dst, agg, E);
    gemm_kernel<128, 128, true, true><<<gemm_blocks, 256>>>(agg, W2, b2, ndst, nullptr, h, N_NODES);

    // Layer 3 (reordered): t = norm_src * (h2 @ W3); out = segsum(t)*norm_dst + b3
    gemm_kernel<128, 64, false, false><<<gemm_blocks, 128>>>(h, W3, nullptr, nullptr, nsrc, agg, N_NODES);

    const int o4 = N_NODES * ODIM / 4;
    zero_kernel<<<(o4 + TB - 1) / TB, TB>>>(out, o4);
    scatter64_kernel<<<(E * 16 + TB - 1) / TB, TB>>>(agg, src, dst, out, E);
    finalize_kernel<<<(o4 + TB - 1) / TB, TB>>>(out, b3);
}

// round 2
// speedup vs baseline: 1.0371x; 1.0371x over previous
#include <cuda_runtime.h>
#include <cstdint>

#define N_NODES 50000
#define DIM 128
#define ODIM 64

// Scratch (static device globals; no allocation).
__device__ float g_h[(size_t)N_NODES * DIM];     // layer activations
__device__ float g_agg1[(size_t)N_NODES * DIM];  // aggregation buffer A
__device__ float g_agg2[(size_t)N_NODES * DIM];  // aggregation buffer B
__device__ float g_norm_src[N_NODES];
__device__ float g_norm_dst[N_NODES];
__device__ float g_outdeg[N_NODES];
__device__ float g_indeg[N_NODES];

// ---------------------------------------------------------------------------
// One up-front zero kernel: agg1, agg2, out, degrees
// ---------------------------------------------------------------------------
__global__ void zero_all_kernel(float* __restrict__ out) {
    const int stride = gridDim.x * blockDim.x;
    int t = blockIdx.x * blockDim.x + threadIdx.x;
    const int n_agg = N_NODES * DIM / 4;   // 1.6M float4 each
    const int n_out = N_NODES * ODIM / 4;  // 0.8M float4
    float4 z = make_float4(0.f, 0.f, 0.f, 0.f);
    for (int i = t; i < n_agg; i += stride) {
        reinterpret_cast<float4*>(g_agg1)[i] = z;
        reinterpret_cast<float4*>(g_agg2)[i] = z;
    }
    for (int i = t; i < n_out; i += stride)
        reinterpret_cast<float4*>(out)[i] = z;
    for (int i = t; i < N_NODES; i += stride) {
        g_outdeg[i] = 0.f;
        g_indeg[i]  = 0.f;
    }
}

__global__ void deg_kernel(const int* __restrict__ src, const int* __restrict__ dst, int E) {
    int i = blockIdx.x * blockDim.x + threadIdx.x;
    if (i < E) {
        atomicAdd(&g_outdeg[src[i]], 1.f);
        atomicAdd(&g_indeg[dst[i]], 1.f);
    }
}

__global__ void norm_kernel() {
    int i = blockIdx.x * blockDim.x + threadIdx.x;
    if (i < N_NODES) {
        g_norm_src[i] = rsqrtf(fmaxf(g_outdeg[i], 1.f));
        g_norm_dst[i] = rsqrtf(fmaxf(g_indeg[i], 1.f));
    }
}

// ---------------------------------------------------------------------------
// Edge scatter: one warp per edge (128 dims), vectorized L2 reduction
// ---------------------------------------------------------------------------
template <bool SCALE_SRC>
__global__ void scatter128_kernel(const float* __restrict__ x,
                                  const int* __restrict__ src,
                                  const int* __restrict__ dst,
                                  float* __restrict__ agg, int E) {
    int w = (blockIdx.x * blockDim.x + threadIdx.x) >> 5;
    if (w >= E) return;
    int lane = threadIdx.x & 31;
    int s = __ldg(src + w);
    int d = __ldg(dst + w);
    float4 v = __ldg(reinterpret_cast<const float4*>(x + (size_t)s * DIM) + lane);
    if (SCALE_SRC) {
        float sc = __ldg(&g_norm_src[s]);
        v.x *= sc; v.y *= sc; v.z *= sc; v.w *= sc;
    }
    float* p = agg + (size_t)d * DIM + lane * 4;
    asm volatile("red.global.add.v4.f32 [%0], {%1, %2, %3, %4};"
                 :: "l"(p), "f"(v.x), "f"(v.y), "f"(v.z), "f"(v.w) : "memory");
}

// 64-dim scatter: half-warp per edge
__global__ void scatter64_kernel(const float* __restrict__ x,
                                 const int* __restrict__ src,
                                 const int* __restrict__ dst,
                                 float* __restrict__ agg, int E) {
    int t = blockIdx.x * blockDim.x + threadIdx.x;
    int e = t >> 4;
    if (e >= E) return;
    int sub = t & 15;
    int s = __ldg(src + e);
    int d = __ldg(dst + e);
    float4 v = __ldg(reinterpret_cast<const float4*>(x + (size_t)s * ODIM) + sub);
    float* p = agg + (size_t)d * ODIM + sub * 4;
    asm volatile("red.global.add.v4.f32 [%0], {%1, %2, %3, %4};"
                 :: "l"(p), "f"(v.x), "f"(v.y), "f"(v.z), "f"(v.w) : "memory");
}

// ---------------------------------------------------------------------------
// TF32 tensor-core GEMM: out = post * act(pre*in @ W + bias)
// Block: 64 rows x N cols, 4 warps, each warp 64 rows x N/4 cols.
// Whole K=128 staged in smem (A tile + W^T), mma.sync.m16n8k8.tf32.
// ---------------------------------------------------------------------------
__device__ __forceinline__ uint32_t f2tf32(float f) {
    uint32_t r;
    asm("cvt.rna.tf32.f32 %0, %1;" : "=r"(r) : "f"(f));
    return r;
}

__device__ __forceinline__ void mma_tf32(float c[4], const uint32_t a[4], const uint32_t b[2]) {
    asm volatile(
        "mma.sync.aligned.m16n8k8.row.col.f32.tf32.tf32.f32 "
        "{%0,%1,%2,%3}, {%4,%5,%6,%7}, {%8,%9}, {%0,%1,%2,%3};"
        : "+f"(c[0]), "+f"(c[1]), "+f"(c[2]), "+f"(c[3])
        : "r"(a[0]), "r"(a[1]), "r"(a[2]), "r"(a[3]), "r"(b[0]), "r"(b[1]));
}

template <int N, bool RELU, bool BIAS, bool PRE, bool POST>
__global__ void __launch_bounds__(128, 1)
gemm_tf32_kernel(const float* __restrict__ in,
                 const float* __restrict__ W,
                 const float* __restrict__ bias,
                 const float* __restrict__ pre_scale,
                 const float* __restrict__ post_scale,
                 float* __restrict__ out, int nrows) {
    constexpr int K  = 128;
    constexpr int SA = K + 4;       // padded stride (floats) for both sA rows and sW^T rows
    constexpr int NT = N / 32;      // n-tiles (of 8 cols) per warp

    extern __shared__ uint32_t smem[];
    uint32_t* sA = smem;             // [64][SA]  A tile, tf32 bits, row-major
    uint32_t* sW = smem + 64 * SA;   // [N][SA]   W transposed: sW[n][k]

    const int tid  = threadIdx.x;
    const int row0 = blockIdx.x * 64;

    // Stage A tile (64 x 128) with optional per-row pre-scale, tf32-converted.
#pragma unroll
    for (int i = tid; i < 64 * (K / 4); i += 128) {
        int r  = i / (K / 4);
        int kk = i % (K / 4);
        int row = row0 + r;
        float4 v = make_float4(0.f, 0.f, 0.f, 0.f);
        if (row < nrows) {
            v = __ldg(reinterpret_cast<const float4*>(in + (size_t)row * K) + kk);
            if (PRE) {
                float ps = __ldg(&pre_scale[row]);
                v.x *= ps; v.y *= ps; v.z *= ps; v.w *= ps;
            }
        }
        uint32_t* p = sA + r * SA + kk * 4;
        p[0] = f2tf32(v.x); p[1] = f2tf32(v.y); p[2] = f2tf32(v.z); p[3] = f2tf32(v.w);
    }
    // Stage W transposed (K x N -> sW[n][k]), tf32-converted.
#pragma unroll
    for (int i = tid; i < K * (N / 4); i += 128) {
        int k  = i / (N / 4);
        int nb = i % (N / 4);
        float4 v = __ldg(reinterpret_cast<const float4*>(W + (size_t)k * N) + nb);
        sW[(nb * 4 + 0) * SA + k] = f2tf32(v.x);
        sW[(nb * 4 + 1) * SA + k] = f2tf32(v.y);
        sW[(nb * 4 + 2) * SA + k] = f2tf32(v.z);
        sW[(nb * 4 + 3) * SA + k] = f2tf32(v.w);
    }
    __syncthreads();

    const int warp = tid >> 5;
    const int lane = tid & 31;
    const int g    = lane >> 2;   // group id 0..7
    const int tg   = lane & 3;    // thread-in-group 0..3
    const int ncol0 = warp * (N / 4);

    float acc[4][NT][4];
#pragma unroll
    for (int m = 0; m < 4; m++)
#pragma unroll
        for (int n = 0; n < NT; n++) {
            acc[m][n][0] = 0.f; acc[m][n][1] = 0.f; acc[m][n][2] = 0.f; acc[m][n][3] = 0.f;
        }

#pragma unroll
    for (int k0 = 0; k0 < K; k0 += 8) {
        uint32_t a[4][4];
#pragma unroll
        for (int m = 0; m < 4; m++) {
            const uint32_t* base = sA + (m * 16 + g) * SA + k0 + tg;
            a[m][0] = base[0];
            a[m][1] = base[8 * SA];
            a[m][2] = base[4];
            a[m][3] = base[8 * SA + 4];
        }
        uint32_t b[NT][2];
#pragma unroll
        for (int n = 0; n < NT; n++) {
            const uint32_t* base = sW + (ncol0 + n * 8 + g) * SA + k0 + tg;
            b[n][0] = base[0];
            b[n][1] = base[4];
        }
#pragma unroll
        for (int m = 0; m < 4; m++)
#pragma unroll
            for (int n = 0; n < NT; n++)
                mma_tf32(acc[m][n], a[m], b[n]);
    }

    // Epilogue: c0,c1 at (row=g, col=2*tg,2*tg+1); c2,c3 at row=g+8.
#pragma unroll
    for (int m = 0; m < 4; m++) {
#pragma unroll
        for (int half = 0; half < 2; half++) {
            int row = row0 + m * 16 + g + half * 8;
            if (row >= nrows) continue;
            float ps = POST ? __ldg(&post_scale[row]) : 1.f;
#pragma unroll
            for (int n = 0; n < NT; n++) {
                int col = ncol0 + n * 8 + 2 * tg;
                float2 o;
                o.x = acc[m][n][half * 2 + 0];
                o.y = acc[m][n][half * 2 + 1];
                if (BIAS) {
                    float2 bv = *reinterpret_cast<const float2*>(bias + col);
                    o.x += bv.x; o.y += bv.y;
                }
                if (RELU) { o.x = fmaxf(o.x, 0.f); o.y = fmaxf(o.y, 0.f); }
                if (POST) { o.x *= ps; o.y *= ps; }
                *reinterpret_cast<float2*>(out + (size_t)row * N + col) = o;
            }
        }
    }
}

// final: out = out * norm_dst[row] + b3
__global__ void finalize_kernel(float* __restrict__ out, const float* __restrict__ b3) {
    int t = blockIdx.x * blockDim.x + threadIdx.x;
    constexpr int J = ODIM / 4;
    if (t >= N_NODES * J) return;
    int i = t / J;
    int j = t % J;
    float nd = g_norm_dst[i];
    float4* p = reinterpret_cast<float4*>(out + (size_t)i * ODIM) + j;
    float4 v = *p;
    float4 b = __ldg(reinterpret_cast<const float4*>(b3) + j);
    v.x = fmaf(v.x, nd, b.x);
    v.y = fmaf(v.y, nd, b.y);
    v.z = fmaf(v.z, nd, b.z);
    v.w = fmaf(v.w, nd, b.w);
    *p = v;
}

// ---------------------------------------------------------------------------
extern "C" void kernel_launch(void* const* d_in, const int* in_sizes, int n_in,
                              void* d_out, int out_size) {
    const float* features = (const float*)d_in[0];
    const float* W1 = (const float*)d_in[1];
    const float* b1 = (const float*)d_in[2];
    const float* W2 = (const float*)d_in[3];
    const float* b2 = (const float*)d_in[4];
    const float* W3 = (const float*)d_in[5];
    const float* b3 = (const float*)d_in[6];
    const int* src  = (const int*)d_in[7];
    const int* dst  = (const int*)d_in[8];
    const int E = in_sizes[7];
    float* out = (float*)d_out;

    float *h, *agg1, *agg2, *nsrc, *ndst;
    cudaGetSymbolAddress((void**)&h,    g_h);
    cudaGetSymbolAddress((void**)&agg1, g_agg1);
    cudaGetSymbolAddress((void**)&agg2, g_agg2);
    cudaGetSymbolAddress((void**)&nsrc, g_norm_src);
    cudaGetSymbolAddress((void**)&ndst, g_norm_dst);

    // Dynamic smem for tf32 GEMMs: (64 + N) * (K+4) * 4 bytes
    const int smem128 = (64 + 128) * 132 * 4;   // 101376
    const int smem64  = (64 + 64)  * 132 * 4;   // 67584
    cudaFuncSetAttribute(gemm_tf32_kernel<128, true,  true,  true, true>,
                         cudaFuncAttributeMaxDynamicSharedMemorySize, smem128);
    cudaFuncSetAttribute(gemm_tf32_kernel<128, true,  true,  true, false>,
                         cudaFuncAttributeMaxDynamicSharedMemorySize, smem128);
    cudaFuncSetAttribute(gemm_tf32_kernel<64,  false, false, false, true>,
                         cudaFuncAttributeMaxDynamicSharedMemorySize, smem64);

    const int TB = 256;
    const int gemm_blocks = (N_NODES + 63) / 64;  // 782

    // Zeros (agg1, agg2, out, degrees) in one pass, then degrees + norms.
    zero_all_kernel<<<1184, TB>>>(out);
    deg_kernel<<<(E + TB - 1) / TB, TB>>>(src, dst, E);
    norm_kernel<<<(N_NODES + TB - 1) / TB, TB>>>();

    // Layer 1: agg1 = segsum(norm_src*features); h = norm_src*relu(norm_dst*agg1 @ W1 + b1)
    scatter128_kernel<true><<<(E * 32 + TB - 1) / TB, TB>>>(features, src, dst, agg1, E);
    gemm_tf32_kernel<128, true, true, true, true>
        <<<gemm_blocks, 128, smem128>>>(agg1, W1, b1, ndst, nsrc, h, N_NODES);

    // Layer 2: agg2 = segsum(h); h = relu(norm_dst*agg2 @ W2 + b2)  (norm_src folded into h)
    scatter128_kernel<false><<<(E * 32 + TB - 1) / TB, TB>>>(h, src, dst, agg2, E);
    gemm_tf32_kernel<128, true, true, true, false>
        <<<gemm_blocks, 128, smem128>>>(agg2, W2, b2, ndst, nullptr, h, N_NODES);

    // Layer 3 (reordered): t = norm_src * (h @ W3); out = norm_dst * segsum(t) + b3
    gemm_tf32_kernel<64, false, false, false, true>
        <<<gemm_blocks, 128, smem64>>>(h, W3, nullptr, nullptr, nsrc, agg1, N_NODES);
    scatter64_kernel<<<(E * 16 + TB - 1) / TB, TB>>>(agg1, src, dst, out, E);

    const int o4 = N_NODES * ODIM / 4;
    finalize_kernel<<<(o4 + TB - 1) / TB, TB>>>(out, b3);
}

// round 3
// speedup vs baseline: 1.9272x; 1.8582x over previous
#include <cuda_runtime.h>
#include <cstdint>

#define N_NODES 50000
#define DIM 128
#define ODIM 64
#define E_CAP 1048576
#define NB_SCAN ((N_NODES + 1023) / 1024)   // 49

// Scratch (static device globals; no allocation).
__device__ float g_h[(size_t)N_NODES * DIM];     // layer activations
__device__ float g_agg[(size_t)N_NODES * DIM];   // aggregation / pre-scatter buffer
__device__ float g_norm_src[N_NODES];
__device__ float g_norm_dst[N_NODES];
__device__ int   g_indeg[N_NODES];
__device__ int   g_outdeg[N_NODES];
__device__ int   g_incl[N_NODES];     // block-inclusive scan temp
__device__ int   g_btot[64];
__device__ int   g_boff[64];
__device__ int   g_rowstart[N_NODES];
__device__ int   g_cursor[N_NODES];
__device__ int   g_esrc[E_CAP];       // CSR: src ids sorted by dst

// ---------------------------------------------------------------------------
// Degrees
// ---------------------------------------------------------------------------
__global__ void zero_deg_kernel() {
    int i = blockIdx.x * blockDim.x + threadIdx.x;
    if (i < N_NODES) { g_indeg[i] = 0; g_outdeg[i] = 0; }
}

__global__ void deg_kernel(const int* __restrict__ src, const int* __restrict__ dst, int E) {
    int i = blockIdx.x * blockDim.x + threadIdx.x;
    if (i < E) {
        atomicAdd(&g_outdeg[src[i]], 1);
        atomicAdd(&g_indeg[dst[i]], 1);
    }
}

// ---------------------------------------------------------------------------
// Prefix scan over indeg -> rowstart (exclusive); also cursors + norms
// ---------------------------------------------------------------------------
__global__ void scan1_kernel() {
    __shared__ int sm[1024];
    int idx = blockIdx.x * 1024 + threadIdx.x;
    int v = (idx < N_NODES) ? g_indeg[idx] : 0;
    sm[threadIdx.x] = v;
    __syncthreads();
#pragma unroll
    for (int off = 1; off < 1024; off <<= 1) {
        int t = (threadIdx.x >= off) ? sm[threadIdx.x - off] : 0;
        __syncthreads();
        sm[threadIdx.x] += t;
        __syncthreads();
    }
    if (idx < N_NODES) g_incl[idx] = sm[threadIdx.x];
    if (threadIdx.x == 1023) g_btot[blockIdx.x] = sm[1023];
}

__global__ void scan2_kernel() {
    if (threadIdx.x == 0) {
        int s = 0;
        for (int b = 0; b < NB_SCAN; b++) { g_boff[b] = s; s += g_btot[b]; }
    }
}

__global__ void scan3_kernel() {
    int idx = blockIdx.x * blockDim.x + threadIdx.x;
    if (idx >= N_NODES) return;
    int ind = g_indeg[idx];
    int excl = g_incl[idx] - ind + g_boff[idx >> 10];
    g_rowstart[idx] = excl;
    g_cursor[idx]   = excl;
    g_norm_dst[idx] = rsqrtf(fmaxf((float)ind, 1.f));
    g_norm_src[idx] = rsqrtf(fmaxf((float)g_outdeg[idx], 1.f));
}

__global__ void place_kernel(const int* __restrict__ src, const int* __restrict__ dst, int E) {
    int e = blockIdx.x * blockDim.x + threadIdx.x;
    if (e >= E) return;
    int d = dst[e];
    int pos = atomicAdd(&g_cursor[d], 1);
    if (pos < E_CAP) g_esrc[pos] = src[e];
}

// ---------------------------------------------------------------------------
// CSR aggregation, 128 dims: one warp per dst node, register accumulation.
// agg[n] = norm_dst[n] * sum_{s in N(n)} (SCALE? norm_src[s] : 1) * x[s]
// ---------------------------------------------------------------------------
template <bool SCALE_SRC>
__global__ void agg128_kernel(const float* __restrict__ x, float* __restrict__ agg) {
    int w = (blockIdx.x * blockDim.x + threadIdx.x) >> 5;
    if (w >= N_NODES) return;
    int lane = threadIdx.x & 31;
    int beg = g_rowstart[w];
    int end = beg + g_indeg[w];
    const float4* X = reinterpret_cast<const float4*>(x);
    float4 acc = make_float4(0.f, 0.f, 0.f, 0.f);

    int i = beg;
    for (; i + 4 <= end; i += 4) {
        int s0 = __ldg(g_esrc + i + 0);
        int s1 = __ldg(g_esrc + i + 1);
        int s2 = __ldg(g_esrc + i + 2);
        int s3 = __ldg(g_esrc + i + 3);
        float4 v0 = __ldg(X + (size_t)s0 * 32 + lane);
        float4 v1 = __ldg(X + (size_t)s1 * 32 + lane);
        float4 v2 = __ldg(X + (size_t)s2 * 32 + lane);
        float4 v3 = __ldg(X + (size_t)s3 * 32 + lane);
        float c0 = SCALE_SRC ? __ldg(g_norm_src + s0) : 1.f;
        float c1 = SCALE_SRC ? __ldg(g_norm_src + s1) : 1.f;
        float c2 = SCALE_SRC ? __ldg(g_norm_src + s2) : 1.f;
        float c3 = SCALE_SRC ? __ldg(g_norm_src + s3) : 1.f;
        acc.x = fmaf(c0, v0.x, acc.x); acc.y = fmaf(c0, v0.y, acc.y);
        acc.z = fmaf(c0, v0.z, acc.z); acc.w = fmaf(c0, v0.w, acc.w);
        acc.x = fmaf(c1, v1.x, acc.x); acc.y = fmaf(c1, v1.y, acc.y);
        acc.z = fmaf(c1, v1.z, acc.z); acc.w = fmaf(c1, v1.w, acc.w);
        acc.x = fmaf(c2, v2.x, acc.x); acc.y = fmaf(c2, v2.y, acc.y);
        acc.z = fmaf(c2, v2.z, acc.z); acc.w = fmaf(c2, v2.w, acc.w);
        acc.x = fmaf(c3, v3.x, acc.x); acc.y = fmaf(c3, v3.y, acc.y);
        acc.z = fmaf(c3, v3.z, acc.z); acc.w = fmaf(c3, v3.w, acc.w);
    }
    for (; i < end; i++) {
        int s = __ldg(g_esrc + i);
        float4 v = __ldg(X + (size_t)s * 32 + lane);
        float c = SCALE_SRC ? __ldg(g_norm_src + s) : 1.f;
        acc.x = fmaf(c, v.x, acc.x); acc.y = fmaf(c, v.y, acc.y);
        acc.z = fmaf(c, v.z, acc.z); acc.w = fmaf(c, v.w, acc.w);
    }
    float nd = g_norm_dst[w];
    acc.x *= nd; acc.y *= nd; acc.z *= nd; acc.w *= nd;
    reinterpret_cast<float4*>(agg)[(size_t)w * 32 + lane] = acc;
}

// CSR aggregation, 64 dims: two nodes per warp (16 lanes each), + bias epilogue.
// out[n] = norm_dst[n] * sum x[s] + b3
__global__ void agg64_kernel(const float* __restrict__ x,
                             const float* __restrict__ b3,
                             float* __restrict__ out) {
    int w = (blockIdx.x * blockDim.x + threadIdx.x) >> 5;
    int sub = (threadIdx.x >> 4) & 1;
    int lane = threadIdx.x & 15;
    int n = w * 2 + sub;
    if (n >= N_NODES) return;
    int beg = g_rowstart[n];
    int end = beg + g_indeg[n];
    const float4* X = reinterpret_cast<const float4*>(x);
    float4 acc = make_float4(0.f, 0.f, 0.f, 0.f);

    int i = beg;
    for (; i + 4 <= end; i += 4) {
        int s0 = __ldg(g_esrc + i + 0);
        int s1 = __ldg(g_esrc + i + 1);
        int s2 = __ldg(g_esrc + i + 2);
        int s3 = __ldg(g_esrc + i + 3);
        float4 v0 = __ldg(X + (size_t)s0 * 16 + lane);
        float4 v1 = __ldg(X + (size_t)s1 * 16 + lane);
        float4 v2 = __ldg(X + (size_t)s2 * 16 + lane);
        float4 v3 = __ldg(X + (size_t)s3 * 16 + lane);
        acc.x += v0.x + v1.x + v2.x + v3.x;
        acc.y += v0.y + v1.y + v2.y + v3.y;
        acc.z += v0.z + v1.z + v2.z + v3.z;
        acc.w += v0.w + v1.w + v2.w + v3.w;
    }
    for (; i < end; i++) {
        int s = __ldg(g_esrc + i);
        float4 v = __ldg(X + (size_t)s * 16 + lane);
        acc.x += v.x; acc.y += v.y; acc.z += v.z; acc.w += v.w;
    }
    float nd = g_norm_dst[n];
    float4 b = __ldg(reinterpret_cast<const float4*>(b3) + lane);
    float4 o;
    o.x = fmaf(acc.x, nd, b.x);
    o.y = fmaf(acc.y, nd, b.y);
    o.z = fmaf(acc.z, nd, b.z);
    o.w = fmaf(acc.w, nd, b.w);
    reinterpret_cast<float4*>(out)[(size_t)n * 16 + lane] = o;
}

// ---------------------------------------------------------------------------
// TF32 tensor-core GEMM: out = post * act(in @ W + bias)
// Block: 128 rows x N cols, 8 warps (2 m-groups x 4 n-groups).
// Whole K=128 staged in smem (A tile + W^T), mma.sync.m16n8k8.tf32.
// ---------------------------------------------------------------------------
__device__ __forceinline__ uint32_t f2tf32(float f) {
    uint32_t r;
    asm("cvt.rna.tf32.f32 %0, %1;" : "=r"(r) : "f"(f));
    return r;
}

__device__ __forceinline__ void mma_tf32(float c[4], const uint32_t a[4], const uint32_t b[2]) {
    asm volatile(
        "mma.sync.aligned.m16n8k8.row.col.f32.tf32.tf32.f32 "
        "{%0,%1,%2,%3}, {%4,%5,%6,%7}, {%8,%9}, {%0,%1,%2,%3};"
        : "+f"(c[0]), "+f"(c[1]), "+f"(c[2]), "+f"(c[3])
        : "r"(a[0]), "r"(a[1]), "r"(a[2]), "r"(a[3]), "r"(b[0]), "r"(b[1]));
}

template <int N, bool RELU, bool BIAS, bool POST>
__global__ void __launch_bounds__(256, 1)
gemm_tf32_kernel(const float* __restrict__ in,
                 const float* __restrict__ W,
                 const float* __restrict__ bias,
                 const float* __restrict__ post_scale,
                 float* __restrict__ out, int nrows) {
    constexpr int K  = 128;
    constexpr int SA = K + 4;
    constexpr int NT = N / 32;     // 8-col n-tiles per warp (warp covers N/4 cols)
    constexpr int ROWS = 128;

    extern __shared__ uint32_t smem[];
    uint32_t* sA = smem;               // [ROWS][SA]
    uint32_t* sW = smem + ROWS * SA;   // [N][SA]   (W transposed)

    const int tid  = threadIdx.x;
    const int row0 = blockIdx.x * ROWS;

    // Stage A tile (tf32-converted).
#pragma unroll
    for (int i = tid; i < ROWS * (K / 4); i += 256) {
        int r  = i / (K / 4);
        int kk = i % (K / 4);
        int row = row0 + r;
        float4 v = make_float4(0.f, 0.f, 0.f, 0.f);
        if (row < nrows)
            v = __ldg(reinterpret_cast<const float4*>(in + (size_t)row * K) + kk);
        uint32_t* p = sA + r * SA + kk * 4;
        p[0] = f2tf32(v.x); p[1] = f2tf32(v.y); p[2] = f2tf32(v.z); p[3] = f2tf32(v.w);
    }
    // Stage W transposed.
#pragma unroll
    for (int i = tid; i < K * (N / 4); i += 256) {
        int k  = i / (N / 4);
        int nb = i % (N / 4);
        float4 v = __ldg(reinterpret_cast<const float4*>(W + (size_t)k * N) + nb);
        sW[(nb * 4 + 0) * SA + k] = f2tf32(v.x);
        sW[(nb * 4 + 1) * SA + k] = f2tf32(v.y);
        sW[(nb * 4 + 2) * SA + k] = f2tf32(v.z);
        sW[(nb * 4 + 3) * SA + k] = f2tf32(v.w);
    }
    __syncthreads();

    const int warp   = tid >> 5;
    const int lane   = tid & 31;
    const int warp_m = warp >> 2;       // 0..1
    const int warp_n = warp & 3;        // 0..3
    const int g      = lane >> 2;
    const int tg     = lane & 3;
    const int rbase  = warp_m * 64;
    const int ncol0  = warp_n * (N / 4);

    float acc[4][NT][4];
#pragma unroll
    for (int m = 0; m < 4; m++)
#pragma unroll
        for (int n = 0; n < NT; n++) {
            acc[m][n][0] = 0.f; acc[m][n][1] = 0.f; acc[m][n][2] = 0.f; acc[m][n][3] = 0.f;
        }

#pragma unroll
    for (int k0 = 0; k0 < K; k0 += 8) {
        uint32_t a[4][4];
#pragma unroll
        for (int m = 0; m < 4; m++) {
            const uint32_t* base = sA + (rbase + m * 16 + g) * SA + k0 + tg;
            a[m][0] = base[0];
            a[m][1] = base[8 * SA];
            a[m][2] = base[4];
            a[m][3] = base[8 * SA + 4];
        }
        uint32_t b[NT][2];
#pragma unroll
        for (int n = 0; n < NT; n++) {
            const uint32_t* base = sW + (ncol0 + n * 8 + g) * SA + k0 + tg;
            b[n][0] = base[0];
            b[n][1] = base[4];
        }
#pragma unroll
        for (int m = 0; m < 4; m++)
#pragma unroll
            for (int n = 0; n < NT; n++)
                mma_tf32(acc[m][n], a[m], b[n]);
    }

#pragma unroll
    for (int m = 0; m < 4; m++) {
#pragma unroll
        for (int half = 0; half < 2; half++) {
            int row = row0 + rbase + m * 16 + g + half * 8;
            if (row >= nrows) continue;
            float ps = POST ? __ldg(&post_scale[row]) : 1.f;
#pragma unroll
            for (int n = 0; n < NT; n++) {
                int col = ncol0 + n * 8 + 2 * tg;
                float2 o;
                o.x = acc[m][n][half * 2 + 0];
                o.y = acc[m][n][half * 2 + 1];
                if (BIAS) {
                    float2 bv = *reinterpret_cast<const float2*>(bias + col);
                    o.x += bv.x; o.y += bv.y;
                }
                if (RELU) { o.x = fmaxf(o.x, 0.f); o.y = fmaxf(o.y, 0.f); }
                if (POST) { o.x *= ps; o.y *= ps; }
                *reinterpret_cast<float2*>(out + (size_t)row * N + col) = o;
            }
        }
    }
}

// ---------------------------------------------------------------------------
extern "C" void kernel_launch(void* const* d_in, const int* in_sizes, int n_in,
                              void* d_out, int out_size) {
    const float* features = (const float*)d_in[0];
    const float* W1 = (const float*)d_in[1];
    const float* b1 = (const float*)d_in[2];
    const float* W2 = (const float*)d_in[3];
    const float* b2 = (const float*)d_in[4];
    const float* W3 = (const float*)d_in[5];
    const float* b3 = (const float*)d_in[6];
    const int* src  = (const int*)d_in[7];
    const int* dst  = (const int*)d_in[8];
    const int E = in_sizes[7];
    float* out = (float*)d_out;

    float *h, *agg, *nsrc;
    cudaGetSymbolAddress((void**)&h,    g_h);
    cudaGetSymbolAddress((void**)&agg,  g_agg);
    cudaGetSymbolAddress((void**)&nsrc, g_norm_src);

    const int smem128 = (128 + 128) * 132 * 4;   // 135168
    const int smem64  = (128 + 64)  * 132 * 4;   // 101376
    cudaFuncSetAttribute(gemm_tf32_kernel<128, true,  true,  true>,
                         cudaFuncAttributeMaxDynamicSharedMemorySize, smem128);
    cudaFuncSetAttribute(gemm_tf32_kernel<128, true,  true,  false>,
                         cudaFuncAttributeMaxDynamicSharedMemorySize, smem128);
    cudaFuncSetAttribute(gemm_tf32_kernel<64,  false, false, true>,
                         cudaFuncAttributeMaxDynamicSharedMemorySize, smem64);

    const int TB = 256;
    const int gemm_blocks = (N_NODES + 127) / 128;   // 391

    // Build CSR (sorted by dst) + norms.
    zero_deg_kernel<<<(N_NODES + TB - 1) / TB, TB>>>();
    deg_kernel<<<(E + TB - 1) / TB, TB>>>(src, dst, E);
    scan1_kernel<<<NB_SCAN, 1024>>>();
    scan2_kernel<<<1, 32>>>();
    scan3_kernel<<<(N_NODES + TB - 1) / TB, TB>>>();
    place_kernel<<<(E + TB - 1) / TB, TB>>>(src, dst, E);

    // Layer 1: agg = norm_dst*segsum(norm_src*features); h = norm_src*relu(agg@W1+b1)
    agg128_kernel<true><<<(N_NODES * 32 + TB - 1) / TB, TB>>>(features, agg);
    gemm_tf32_kernel<128, true, true, true>
        <<<gemm_blocks, 256, smem128>>>(agg, W1, b1, nsrc, h, N_NODES);

    // Layer 2: agg = norm_dst*segsum(h); h = relu(agg@W2+b2)  (norm_src folded into h)
    agg128_kernel<false><<<(N_NODES * 32 + TB - 1) / TB, TB>>>(h, agg);
    gemm_tf32_kernel<128, true, true, false>
        <<<gemm_blocks, 256, smem128>>>(agg, W2, b2, nullptr, h, N_NODES);

    // Layer 3 (reordered): t = norm_src*(h@W3); out = norm_dst*segsum(t) + b3
    gemm_tf32_kernel<64, false, false, true>
        <<<gemm_blocks, 256, smem64>>>(h, W3, nullptr, nsrc, agg, N_NODES);
    agg64_kernel<<<((N_NODES + 1) / 2 * 32 + TB - 1) / TB, TB>>>(agg, b3, out);
}